// round 6
// baseline (speedup 1.0000x reference)
#include <cuda_runtime.h>
#include <math.h>

// ---------------------------------------------------------------------------
// AliasFreeConv: modulated 3x3 conv (demod) + 2x up (12-tap) + lrelu + 2x down
// B=8, Cin=Cout=512, H=W=64, conv VALID -> 62x62, up -> 128x128, down -> 64x64
//
// Structure:
//   K1 k_style : s[b,ci]  = style @ (mod_w/sqrt(512))^T + mod_b
//   K2 k_wsq   : wsq[co,ci] = sum_k conv_w^2
//   K3 k_demod : g[b,co]  = rsqrt(wscale^2 * sum_ci s^2*wsq + eps)/(1+eps)
//   K4 k_conv  : A[b,co]  = (conv3x3(x * wscale*s, conv_w)) * g + act_b
//   K5 k_filter: whole up/lrelu/down chain per (b,co) plane in shared memory
// ---------------------------------------------------------------------------

#define BATCH 8
#define CIN   512
#define COUT  512
#define HW    64
#define HC    62      // conv output spatial
#define HU    128     // upsampled spatial
#define NTAPS 12

#define LIN_SCALE 0.044194173824159216f   // 1/sqrt(512)
#define WSCALE    0.014731391274719742f   // 1/sqrt(512*9)
#define WSCALE2   2.170138888888889e-4f   // 1/4608
#define EPSV      1e-8f
#define NEG_SLOPE 0.2f
#define LRELU_SC  1.4142135623730951f

// ------------------------- scratch (device globals) ------------------------
__device__ float g_s  [BATCH*CIN];          // modulation scalars
__device__ float g_g  [BATCH*COUT];         // demod/(1+eps)
__device__ float g_wsq[COUT*CIN];           // sum_k conv_w^2
__device__ float g_A  [BATCH*COUT*HC*HC];   // conv output (63 MB)

// ------------------------- K1: s = style @ (mod_w*ls)^T + mod_b ------------
__global__ void k_style(const float* __restrict__ style,
                        const float* __restrict__ mod_w,
                        const float* __restrict__ mod_b) {
    int w    = blockIdx.x * 8 + (threadIdx.x >> 5);   // 4096 warps = (b, c)
    int lane = threadIdx.x & 31;
    int b = w >> 9, c = w & 511;
    const float* sp = style + b * 512;
    const float* mp = mod_w + c * 512;
    float sum = 0.f;
    #pragma unroll 4
    for (int d = lane; d < 512; d += 32) sum += sp[d] * mp[d];
    #pragma unroll
    for (int off = 16; off; off >>= 1) sum += __shfl_xor_sync(0xffffffffu, sum, off);
    if (lane == 0) g_s[w] = sum * LIN_SCALE + mod_b[c];
}

// ------------------------- K2: wsq[co,ci] = sum_k conv_w^2 -----------------
__global__ void k_wsq(const float* __restrict__ cw) {
    int i = blockIdx.x * blockDim.x + threadIdx.x;
    if (i < COUT * CIN) {
        float s = 0.f;
        #pragma unroll
        for (int k = 0; k < 9; k++) { float v = cw[i * 9 + k]; s += v * v; }
        g_wsq[i] = s;
    }
}

// ------------------------- K3: g = demod/(1+eps) ---------------------------
__global__ void k_demod() {
    int w    = blockIdx.x * 8 + (threadIdx.x >> 5);   // 4096 warps = (b, co)
    int lane = threadIdx.x & 31;
    int b = w >> 9, co = w & 511;
    const float* sp = g_s   + b  * 512;
    const float* wq = g_wsq + co * 512;
    float sum = 0.f;
    #pragma unroll 4
    for (int d = lane; d < 512; d += 32) { float sv = sp[d]; sum += sv * sv * wq[d]; }
    #pragma unroll
    for (int off = 16; off; off >>= 1) sum += __shfl_xor_sync(0xffffffffu, sum, off);
    if (lane == 0) g_g[w] = 1.0f / ((1.0f + EPSV) * sqrtf(WSCALE2 * sum + EPSV));
}

// ------------------------- K4: direct 3x3 conv -----------------------------
// Block: 16 output channels x (16 y x 32 x) spatial tile.
// Threads 256: 4 co-subgroups x 64 spatial threads; thread owns 4co x (2y x 4x).
// Input modulation (wscale * s[b,ci]) is applied during smem staging.
#define CO_TILE 16
#define TY 16
#define TX 32
#define CI_STEP 4
#define RS 35                       // padded smem row stride (34 + 1)

__global__ __launch_bounds__(256)
void k_conv(const float* __restrict__ x,
            const float* __restrict__ cw,
            const float* __restrict__ act_b) {
    __shared__ float smin[CI_STEP][18 * RS];
    __shared__ float smw [CI_STEP][CO_TILE * 9];

    int b   = blockIdx.z >> 5;
    int co0 = (blockIdx.z & 31) * CO_TILE;
    int x0  = blockIdx.x * TX;
    int y0  = blockIdx.y * TY;

    int tid = threadIdx.x;
    int cg  = tid >> 6;               // 0..3 (co subgroup, constant per warp)
    int sid = tid & 63;
    int ty  = sid >> 3;               // 0..7
    int tx  = sid & 7;                // 0..7
    int py0 = ty * 2, px0 = tx * 4;

    float acc[4][2][4];
    #pragma unroll
    for (int c = 0; c < 4; c++)
        #pragma unroll
        for (int py = 0; py < 2; py++)
            #pragma unroll
            for (int px = 0; px < 4; px++) acc[c][py][px] = 0.f;

    const float* xb = x + b * (CIN * HW * HW);
    const float* sb = g_s + (b << 9);

    for (int ci0 = 0; ci0 < CIN; ci0 += CI_STEP) {
        __syncthreads();
        // stage input tiles (CI_STEP x 18 x 34), scaled by wscale*s[b,ci];
        // clamp OOB rows/cols (values only feed out-of-range outputs)
        for (int idx = tid; idx < CI_STEP * 18 * 34; idx += 256) {
            int ci  = idx / (18 * 34);
            int rem = idx - ci * (18 * 34);
            int r = rem / 34, c = rem - r * 34;
            int gy = y0 + r; if (gy > 63) gy = 63;
            int gx = x0 + c; if (gx > 63) gx = 63;
            float sc = WSCALE * sb[ci0 + ci];
            smin[ci][r * RS + c] = xb[((ci0 + ci) << 12) + (gy << 6) + gx] * sc;
        }
        // stage weights (CI_STEP x 16co x 9)
        for (int idx = tid; idx < CI_STEP * CO_TILE * 9; idx += 256) {
            int ci  = idx / (CO_TILE * 9);
            int rem = idx - ci * (CO_TILE * 9);
            int col = rem / 9, k = rem - col * 9;
            smw[ci][rem] = cw[((co0 + col) * CIN + ci0 + ci) * 9 + k];
        }
        __syncthreads();

        #pragma unroll
        for (int ci = 0; ci < CI_STEP; ci++) {
            float p[4][6];
            #pragma unroll
            for (int r = 0; r < 4; r++)
                #pragma unroll
                for (int c = 0; c < 6; c++)
                    p[r][c] = smin[ci][(py0 + r) * RS + px0 + c];
            #pragma unroll
            for (int ky = 0; ky < 3; ky++) {
                #pragma unroll
                for (int kx = 0; kx < 3; kx++) {
                    int kk = ky * 3 + kx;
                    float w0 = smw[ci][(cg * 4 + 0) * 9 + kk];
                    float w1 = smw[ci][(cg * 4 + 1) * 9 + kk];
                    float w2 = smw[ci][(cg * 4 + 2) * 9 + kk];
                    float w3 = smw[ci][(cg * 4 + 3) * 9 + kk];
                    #pragma unroll
                    for (int py = 0; py < 2; py++) {
                        #pragma unroll
                        for (int px = 0; px < 4; px++) {
                            float v = p[py + ky][px + kx];
                            acc[0][py][px] += w0 * v;
                            acc[1][py][px] += w1 * v;
                            acc[2][py][px] += w2 * v;
                            acc[3][py][px] += w3 * v;
                        }
                    }
                }
            }
        }
    }

    // epilogue: *demod', +act_b
    #pragma unroll
    for (int c = 0; c < 4; c++) {
        int co = co0 + cg * 4 + c;
        float gg = g_g[b * COUT + co];
        float bb = act_b[co];
        #pragma unroll
        for (int py = 0; py < 2; py++) {
            int oy = y0 + py0 + py;
            if (oy >= HC) continue;
            #pragma unroll
            for (int px = 0; px < 4; px++) {
                int ox = x0 + px0 + px;
                if (ox >= HC) continue;
                g_A[((b * COUT + co) * HC + oy) * HC + ox] = acc[c][py][px] * gg + bb;
            }
        }
    }
}

// ------------------------- K5: fused filter chain --------------------------
// One block per (b,co) plane. Entire pipeline in shared memory:
//   sA[62][62]  --upx-->  sB[62][128]  --upy+lrelu-->  sC[128][128]
//   --downx--> sD[128][64] --downy--> out[64][64]
//
// Index maps (filter symmetric => flip is identity):
//   up  : out[n] = sum_s (2*uf[s]) * in[(n+3-s)/2],  s parity = (n+3)&1
//   down: out[n] = sum_s df[s] * in[2n+6-s]
//
// smem layout (floats):
//   sA  @ 0      size 62*63  = 3906
//   sB  @ 3906   size 62*129 = 7998     (sA+sB end = 11904)
//   sC  @ 11904  size 128*129 = 16512   (end = 28416)
//   sD  @ 0      size 128*65 = 8320     (reuses dead sA/sB region)
//   kfu @ 28416  (12), kfd @ 28428 (12) -> total 28440 floats = 113760 B
#define SMEM_FILT_BYTES (28440 * 4)

__global__ __launch_bounds__(256)
void k_filter(const float* __restrict__ uf, const float* __restrict__ df,
              float* __restrict__ out) {
    extern __shared__ float sm[];
    float* sA  = sm;
    float* sB  = sm + 3906;
    float* sC  = sm + 11904;
    float* sD  = sm;                 // reuse (sA/sB dead by phase 3)
    float* kfu = sm + 28416;
    float* kfd = sm + 28428;

    int p   = blockIdx.x;            // plane = b*512 + co
    int tid = threadIdx.x;

    if (tid < NTAPS)          kfu[tid] = uf[tid] * 2.0f;
    else if (tid < 2 * NTAPS) kfd[tid - NTAPS] = df[tid - NTAPS];

    // phase 0: load A plane
    const float* Ap = g_A + p * (HC * HC);
    for (int i = tid; i < HC * HC; i += 256) {
        int r = i / HC, c = i - r * HC;
        sA[r * 63 + c] = Ap[i];
    }
    __syncthreads();

    // phase 1: upsample x  -> sB[62][128]
    for (int i = tid; i < HC * HU; i += 256) {
        int n = i & 127, y = i >> 7;
        const float* row = sA + y * 63;
        float acc = 0.f;
        int s0 = (n + 3) & 1;
        #pragma unroll
        for (int q = 0; q < 6; q++) {
            int s = s0 + 2 * q;
            int j = (n + 3 - s) >> 1;
            if ((unsigned)j < (unsigned)HC) acc += kfu[s] * row[j];
        }
        sB[y * 129 + n] = acc;
    }
    __syncthreads();

    // phase 2: upsample y + lrelu*sqrt2  -> sC[128][128]
    for (int i = tid; i < HU * HU; i += 256) {
        int xcol = i & 127, m = i >> 7;
        float acc = 0.f;
        int s0 = (m + 3) & 1;
        #pragma unroll
        for (int q = 0; q < 6; q++) {
            int s = s0 + 2 * q;
            int j = (m + 3 - s) >> 1;
            if ((unsigned)j < (unsigned)HC) acc += kfu[s] * sB[j * 129 + xcol];
        }
        acc = (acc >= 0.f ? acc : NEG_SLOPE * acc) * LRELU_SC;
        sC[m * 129 + xcol] = acc;
    }
    __syncthreads();

    // phase 3: downsample x -> sD[128][64]
    for (int i = tid; i < HU * 64; i += 256) {
        int n = i & 63, y = i >> 6;
        const float* row = sC + y * 129;
        float acc = 0.f;
        #pragma unroll
        for (int s = 0; s < NTAPS; s++) {
            int j = 2 * n + 6 - s;
            if ((unsigned)j < (unsigned)HU) acc += kfd[s] * row[j];
        }
        sD[y * 65 + n] = acc;
    }
    __syncthreads();

    // phase 4: downsample y -> out[64][64]
    float* op = out + p * (64 * 64);
    for (int i = tid; i < 64 * 64; i += 256) {
        int xcol = i & 63, m = i >> 6;
        float acc = 0.f;
        #pragma unroll
        for (int s = 0; s < NTAPS; s++) {
            int j = 2 * m + 6 - s;
            if ((unsigned)j < (unsigned)HU) acc += kfd[s] * sD[j * 65 + xcol];
        }
        op[i] = acc;
    }
}

// ---------------------------------------------------------------------------
extern "C" void kernel_launch(void* const* d_in, const int* in_sizes, int n_in,
                              void* d_out, int out_size) {
    const float* x      = (const float*)d_in[0];
    const float* style  = (const float*)d_in[1];
    const float* mod_w  = (const float*)d_in[2];
    const float* mod_b  = (const float*)d_in[3];
    const float* conv_w = (const float*)d_in[4];
    const float* act_b  = (const float*)d_in[5];
    const float* up_f   = (const float*)d_in[6];
    const float* down_f = (const float*)d_in[7];
    float* out = (float*)d_out;

    // opt-in to >48KB dynamic smem for the fused filter kernel (idempotent,
    // immediate host-side call; not a stream op, safe under graph capture)
    cudaFuncSetAttribute(k_filter, cudaFuncAttributeMaxDynamicSharedMemorySize,
                         SMEM_FILT_BYTES);

    k_style<<<512, 256>>>(style, mod_w, mod_b);          // 4096 warps
    k_wsq<<<(COUT * CIN + 255) / 256, 256>>>(conv_w);
    k_demod<<<512, 256>>>();

    dim3 cgrid(2, 4, BATCH * (COUT / CO_TILE));          // (x tiles, y tiles, b*co)
    k_conv<<<cgrid, 256>>>(x, conv_w, act_b);

    k_filter<<<BATCH * COUT, 256, SMEM_FILT_BYTES>>>(up_f, down_f, out);
}

// round 8
// speedup vs baseline: 2.7747x; 2.7747x over previous
#include <cuda_runtime.h>
#include <cuda_bf16.h>
#include <math.h>

// ---------------------------------------------------------------------------
// AliasFreeConv: modulated 3x3 conv (demod) + 2x up (12-tap) + lrelu + 2x down
// Conv: bf16 split-precision (3-pass) implicit GEMM on mma.sync (HMMA).
// (tcgen05 is not compilable here: harness ptxas targets base sm_103.)
// ---------------------------------------------------------------------------

#define BATCH 8
#define CIN   512
#define COUT  512
#define HW    64
#define HC    62
#define HU    128
#define NTAPS 12
#define XP    68              // padded spatial for channels-last input

#define LIN_SCALE 0.044194173824159216f   // 1/sqrt(512)
#define WSCALE    0.014731391274719742f   // 1/sqrt(512*9)
#define WSCALE2   2.170138888888889e-4f   // 1/4608
#define EPSV      1e-8f
#define NEG_SLOPE 0.2f
#define LRELU_SC  1.4142135623730951f

#define XT_ELEMS (BATCH*XP*XP*512)        // 18,939,904
#define WT_ELEMS (9*512*512)              // 2,359,296

// ------------------------- scratch (device globals) ------------------------
__device__ float g_s  [BATCH*CIN];
__device__ float g_g  [BATCH*COUT];
__device__ float g_wsq[COUT*CIN];
__device__ float g_A  [BATCH*COUT*HC*HC];               // conv output (63 MB)
__device__ __align__(16) __nv_bfloat16 g_xhi[XT_ELEMS]; // x*wscale*s, hi part
__device__ __align__(16) __nv_bfloat16 g_xlo[XT_ELEMS]; // lo part
__device__ __align__(16) __nv_bfloat16 g_whi[WT_ELEMS]; // [tap][co][ci]
__device__ __align__(16) __nv_bfloat16 g_wlo[WT_ELEMS];

// ------------------------- PTX helpers -------------------------------------
__device__ __forceinline__ unsigned smem_u32(const void* p) {
    unsigned a;
    asm("{ .reg .u64 t; cvta.to.shared.u64 t, %1; cvt.u32.u64 %0, t; }"
        : "=r"(a) : "l"(p));
    return a;
}
__device__ __forceinline__ void cp16(unsigned dst, const void* src) {
    asm volatile("cp.async.cg.shared.global [%0], [%1], 16;"
                 :: "r"(dst), "l"(src) : "memory");
}
__device__ __forceinline__ void cp_commit() {
    asm volatile("cp.async.commit_group;" ::: "memory");
}
__device__ __forceinline__ void cp_wait0() {
    asm volatile("cp.async.wait_group 0;" ::: "memory");
}
#define MMA16816(d, a0, a1, a2, a3, b0, b1) \
    asm volatile("mma.sync.aligned.m16n8k16.row.col.f32.bf16.bf16.f32 " \
        "{%0,%1,%2,%3}, {%4,%5,%6,%7}, {%8,%9}, {%0,%1,%2,%3};" \
        : "+f"((d)[0]), "+f"((d)[1]), "+f"((d)[2]), "+f"((d)[3]) \
        : "r"(a0), "r"(a1), "r"(a2), "r"(a3), "r"(b0), "r"(b1))

// ------------------------- K1: s = style @ (mod_w*ls)^T + mod_b ------------
__global__ void k_style(const float* __restrict__ style,
                        const float* __restrict__ mod_w,
                        const float* __restrict__ mod_b) {
    int w    = blockIdx.x * 8 + (threadIdx.x >> 5);
    int lane = threadIdx.x & 31;
    int b = w >> 9, c = w & 511;
    const float* sp = style + b * 512;
    const float* mp = mod_w + c * 512;
    float sum = 0.f;
    #pragma unroll 4
    for (int d = lane; d < 512; d += 32) sum += sp[d] * mp[d];
    #pragma unroll
    for (int off = 16; off; off >>= 1) sum += __shfl_xor_sync(0xffffffffu, sum, off);
    if (lane == 0) g_s[w] = sum * LIN_SCALE + mod_b[c];
}

// ------------------------- K2: wsq[co,ci] = sum_k conv_w^2 -----------------
__global__ void k_wsq(const float* __restrict__ cw) {
    int i = blockIdx.x * blockDim.x + threadIdx.x;
    if (i < COUT * CIN) {
        float s = 0.f;
        #pragma unroll
        for (int k = 0; k < 9; k++) { float v = cw[i * 9 + k]; s += v * v; }
        g_wsq[i] = s;
    }
}

// ------------------------- K3: g = demod/(1+eps) ---------------------------
__global__ void k_demod() {
    int w    = blockIdx.x * 8 + (threadIdx.x >> 5);
    int lane = threadIdx.x & 31;
    int b = w >> 9, co = w & 511;
    const float* sp = g_s   + b  * 512;
    const float* wq = g_wsq + co * 512;
    float sum = 0.f;
    #pragma unroll 4
    for (int d = lane; d < 512; d += 32) { float sv = sp[d]; sum += sv * sv * wq[d]; }
    #pragma unroll
    for (int off = 16; off; off >>= 1) sum += __shfl_xor_sync(0xffffffffu, sum, off);
    if (lane == 0) g_g[w] = 1.0f / ((1.0f + EPSV) * sqrtf(WSCALE2 * sum + EPSV));
}

// ------------------------- K4a: zero padded x_t ----------------------------
__global__ void k_zero_xt() {
    uint4 z = make_uint4(0u, 0u, 0u, 0u);
    uint4* a = reinterpret_cast<uint4*>(g_xhi);
    uint4* b = reinterpret_cast<uint4*>(g_xlo);
    int n = XT_ELEMS / 8;
    for (int i = blockIdx.x * blockDim.x + threadIdx.x; i < n;
         i += gridDim.x * blockDim.x) { a[i] = z; b[i] = z; }
}

// ------------------------- K4b: x -> channels-last bf16 hi/lo --------------
__global__ __launch_bounds__(256)
void k_prep_x(const float* __restrict__ x) {
    __shared__ float t[32][33];
    int bid  = blockIdx.x;                 // b(8) * y(64) * ciT(16) * xT(2)
    int xt   = bid & 1;
    int ci_t = (bid >> 1) & 15;
    int y    = (bid >> 5) & 63;
    int b    = bid >> 11;
    int tx = threadIdx.x & 31, ty = threadIdx.x >> 5;   // (32, 8)

    #pragma unroll
    for (int j = 0; j < 4; j++) {
        int ci = ci_t * 32 + ty + 8 * j;
        int xx = xt * 32 + tx;
        float v = x[((((b << 9) + ci) << 6) + y) * 64 + xx];
        t[ty + 8 * j][tx] = v * (WSCALE * g_s[(b << 9) + ci]);
    }
    __syncthreads();
    #pragma unroll
    for (int j = 0; j < 4; j++) {
        int xx = xt * 32 + ty + 8 * j;
        int ci = ci_t * 32 + tx;
        float v = t[tx][ty + 8 * j];
        __nv_bfloat16 hi = __float2bfloat16(v);
        __nv_bfloat16 lo = __float2bfloat16(v - __bfloat162float(hi));
        long o = ((long)(b * XP + y) * XP + xx) * 512 + ci;
        g_xhi[o] = hi;
        g_xlo[o] = lo;
    }
}

// ------------------------- K4c: weights -> [tap][co][ci] bf16 hi/lo --------
__global__ void k_prep_w(const float* __restrict__ cw) {
    int i = blockIdx.x * blockDim.x + threadIdx.x;
    if (i >= WT_ELEMS) return;
    int ci  = i & 511;
    int co  = (i >> 9) & 511;
    int tap = i >> 18;
    float v = cw[(co * 512 + ci) * 9 + tap];
    __nv_bfloat16 hi = __float2bfloat16(v);
    __nv_bfloat16 lo = __float2bfloat16(v - __bfloat162float(hi));
    g_whi[i] = hi;
    g_wlo[i] = lo;
}

// ------------------------- K5: mma.sync conv -------------------------------
// CTA tile: M=128 co x N=128 pixels (8y x 16x). 8 warps = 2(m) x 4(n),
// warp tile 64x32, mma m16n8k16 bf16. K loop: 3 passes x 8 ci-chunks(64)
// x 9 taps = 216 iters of K=64. cp.async double-buffers W per tap; X tile
// (10x18 pixels x 64ci) staged once per (pass,chunk), taps read shifted rows.
//
// smem (bytes): Xs0 @0 (25920 = 180*144), Xs1 @25920,
//               Ws0 @51840 (18432 = 128*144), Ws1 @70272. total 88704.
#define XS_STRIDE 144
#define OFF_WS    51840
#define WS_BYTES  18432
#define XS_BYTES  25920
#define SMEM_CONV2 88704

__global__ __launch_bounds__(256, 2)
void k_conv_mma(const float* __restrict__ act_b) {
    extern __shared__ __align__(16) char smc[];
    unsigned sbase = smem_u32(smc);

    int tid  = threadIdx.x;
    int wid  = tid >> 5, lane = tid & 31;
    int g    = lane >> 2, t4 = lane & 3;      // mma quad layout
    int wm   = wid >> 2;                      // 0..1 -> co offset wm*64
    int wn   = wid & 3;                       // 0..3 -> pixel offset wn*32

    int bidx = blockIdx.x;                    // 1024 = b(8)*coT(4)*yT(8)*xT(4)
    int xT   = bidx & 3;
    int yT   = (bidx >> 2) & 7;
    int coT  = (bidx >> 5) & 3;
    int b    = bidx >> 7;
    int co0  = coT << 7;
    int y0   = yT << 3;                       // output tile origin
    int x0   = xT << 4;

    const __nv_bfloat16* xhiB = g_xhi + (long)b * XP * XP * 512;
    const __nv_bfloat16* xloB = g_xlo + (long)b * XP * XP * 512;

    float acc[4][4][4];
    #pragma unroll
    for (int mi = 0; mi < 4; mi++)
        #pragma unroll
        for (int ni = 0; ni < 4; ni++)
            #pragma unroll
            for (int q = 0; q < 4; q++) acc[mi][ni][q] = 0.f;

    // ---- staging helpers ----
    auto stageW = [&](int it, int buf) {
        int pass = it / 72;
        int r    = it - pass * 72;
        int tap  = r % 9;
        int ci0  = (r / 9) << 6;
        const __nv_bfloat16* wp =
            ((pass == 1) ? g_wlo : g_whi) + ((long)tap << 18) + (long)co0 * 512 + ci0;
        unsigned dst = sbase + OFF_WS + buf * WS_BYTES;
        #pragma unroll
        for (int k = 0; k < 4; k++) {                 // 1024 chunks / 256
            int c = tid + (k << 8);
            int row = c >> 3, cc = c & 7;
            cp16(dst + row * XS_STRIDE + (cc << 4), wp + row * 512 + (cc << 3));
        }
    };
    auto stageX = [&](int j, int buf) {               // j = pass*8 + chunk
        int pass = j >> 3;
        int ci0  = (j & 7) << 6;
        const __nv_bfloat16* xp = ((pass < 2) ? xhiB : xloB) + ci0;
        unsigned dst = sbase + buf * XS_BYTES;
        for (int c = tid; c < 180 * 8; c += 256) {
            int row = c >> 3, cc = c & 7;
            int gy = y0 + row / 18, gx = x0 + row % 18;
            cp16(dst + row * XS_STRIDE + (cc << 4),
                 xp + (long)(gy * XP + gx) * 512 + (cc << 3));
        }
    };

    // prologue
    stageX(0, 0);
    stageW(0, 0);
    cp_commit();
    cp_wait0();
    __syncthreads();

    // per-thread fragment base offsets (within buffers)
    unsigned aTh = (unsigned)((wm * 64 + g) * XS_STRIDE + t4 * 4);
    unsigned bTh = (unsigned)(g * XS_STRIDE + t4 * 4);

    #pragma unroll 1
    for (int i = 0; i < 216; i++) {
        if (i + 1 < 216) stageW(i + 1, (i + 1) & 1);
        if ((i % 9) == 0) {
            int jn = i / 9 + 1;
            if (jn < 24) stageX(jn, jn & 1);
        }
        cp_commit();

        // compute iter i
        {
            int r   = i % 72;
            int tap = r % 9;
            int ky  = tap / 3, kx = tap - 3 * (tap / 3);
            const char* ws = smc + OFF_WS + (i & 1) * WS_BYTES;
            const char* xs = smc + ((i / 9) & 1) * XS_BYTES;

            unsigned rb[4];
            #pragma unroll
            for (int ni = 0; ni < 4; ni++) {
                int p0 = wn * 32 + ni * 8;
                rb[ni] = (unsigned)((((p0 >> 4) + ky) * 18 + (p0 & 15) + kx)
                                    * XS_STRIDE);
            }

            #pragma unroll
            for (int kb = 0; kb < 4; kb++) {
                unsigned bf[4][2];
                #pragma unroll
                for (int ni = 0; ni < 4; ni++) {
                    const char* p = xs + rb[ni] + bTh + kb * 32;
                    bf[ni][0] = *(const unsigned*)p;
                    bf[ni][1] = *(const unsigned*)(p + 16);
                }
                #pragma unroll
                for (int mi = 0; mi < 4; mi++) {
                    const char* pa = ws + aTh + mi * (16 * XS_STRIDE) + kb * 32;
                    unsigned a0 = *(const unsigned*)pa;
                    unsigned a1 = *(const unsigned*)(pa + 8 * XS_STRIDE);
                    unsigned a2 = *(const unsigned*)(pa + 16);
                    unsigned a3 = *(const unsigned*)(pa + 8 * XS_STRIDE + 16);
                    #pragma unroll
                    for (int ni = 0; ni < 4; ni++)
                        MMA16816(acc[mi][ni], a0, a1, a2, a3, bf[ni][0], bf[ni][1]);
                }
            }
        }

        cp_wait0();
        __syncthreads();
    }

    // epilogue: D[co][pix] * demod + bias -> g_A
    #pragma unroll
    for (int mi = 0; mi < 4; mi++) {
        int coL = co0 + wm * 64 + mi * 16 + g;
        int coH = coL + 8;
        float ggL = g_g[(b << 9) + coL], bbL = act_b[coL];
        float ggH = g_g[(b << 9) + coH], bbH = act_b[coH];
        float* apL = g_A + (long)((b << 9) + coL) * (HC * HC);
        float* apH = g_A + (long)((b << 9) + coH) * (HC * HC);
        #pragma unroll
        for (int ni = 0; ni < 4; ni++) {
            int p0 = wn * 32 + ni * 8;
            int py = p0 >> 4, px = (p0 & 15) + 2 * t4;
            int oy = y0 + py, ox = x0 + px;
            if (oy < HC) {
                if (ox < HC) {
                    apL[oy * HC + ox] = acc[mi][ni][0] * ggL + bbL;
                    apH[oy * HC + ox] = acc[mi][ni][2] * ggH + bbH;
                }
                if (ox + 1 < HC) {
                    apL[oy * HC + ox + 1] = acc[mi][ni][1] * ggL + bbL;
                    apH[oy * HC + ox + 1] = acc[mi][ni][3] * ggH + bbH;
                }
            }
        }
    }
}

// ------------------------- K6: fused filter chain --------------------------
#define SMEM_FILT_BYTES (28440 * 4)

__global__ __launch_bounds__(256)
void k_filter(const float* __restrict__ uf, const float* __restrict__ df,
              float* __restrict__ out) {
    extern __shared__ float sm[];
    float* sA  = sm;
    float* sB  = sm + 3906;
    float* sC  = sm + 11904;
    float* sD  = sm;
    float* kfu = sm + 28416;
    float* kfd = sm + 28428;

    int p   = blockIdx.x;
    int tid = threadIdx.x;

    if (tid < NTAPS)          kfu[tid] = uf[tid] * 2.0f;
    else if (tid < 2 * NTAPS) kfd[tid - NTAPS] = df[tid - NTAPS];

    const float* Ap = g_A + (long)p * (HC * HC);
    for (int i = tid; i < HC * HC; i += 256) {
        int r = i / HC, c = i - r * HC;
        sA[r * 63 + c] = Ap[i];
    }
    __syncthreads();

    for (int i = tid; i < HC * HU; i += 256) {
        int n = i & 127, y = i >> 7;
        const float* row = sA + y * 63;
        float acc = 0.f;
        int s0 = (n + 3) & 1;
        #pragma unroll
        for (int q = 0; q < 6; q++) {
            int s = s0 + 2 * q;
            int j = (n + 3 - s) >> 1;
            if ((unsigned)j < (unsigned)HC) acc += kfu[s] * row[j];
        }
        sB[y * 129 + n] = acc;
    }
    __syncthreads();

    for (int i = tid; i < HU * HU; i += 256) {
        int xcol = i & 127, m = i >> 7;
        float acc = 0.f;
        int s0 = (m + 3) & 1;
        #pragma unroll
        for (int q = 0; q < 6; q++) {
            int s = s0 + 2 * q;
            int j = (m + 3 - s) >> 1;
            if ((unsigned)j < (unsigned)HC) acc += kfu[s] * sB[j * 129 + xcol];
        }
        acc = (acc >= 0.f ? acc : NEG_SLOPE * acc) * LRELU_SC;
        sC[m * 129 + xcol] = acc;
    }
    __syncthreads();

    for (int i = tid; i < HU * 64; i += 256) {
        int n = i & 63, y = i >> 6;
        const float* row = sC + y * 129;
        float acc = 0.f;
        #pragma unroll
        for (int s = 0; s < NTAPS; s++) {
            int j = 2 * n + 6 - s;
            if ((unsigned)j < (unsigned)HU) acc += kfd[s] * row[j];
        }
        sD[y * 65 + n] = acc;
    }
    __syncthreads();

    float* op = out + (long)p * (64 * 64);
    for (int i = tid; i < 64 * 64; i += 256) {
        int xcol = i & 63, m = i >> 6;
        float acc = 0.f;
        #pragma unroll
        for (int s = 0; s < NTAPS; s++) {
            int j = 2 * m + 6 - s;
            if ((unsigned)j < (unsigned)HU) acc += kfd[s] * sD[j * 65 + xcol];
        }
        op[i] = acc;
    }
}

// ---------------------------------------------------------------------------
extern "C" void kernel_launch(void* const* d_in, const int* in_sizes, int n_in,
                              void* d_out, int out_size) {
    const float* x      = (const float*)d_in[0];
    const float* style  = (const float*)d_in[1];
    const float* mod_w  = (const float*)d_in[2];
    const float* mod_b  = (const float*)d_in[3];
    const float* conv_w = (const float*)d_in[4];
    const float* act_b  = (const float*)d_in[5];
    const float* up_f   = (const float*)d_in[6];
    const float* down_f = (const float*)d_in[7];
    float* out = (float*)d_out;

    cudaFuncSetAttribute(k_filter, cudaFuncAttributeMaxDynamicSharedMemorySize,
                         SMEM_FILT_BYTES);
    cudaFuncSetAttribute(k_conv_mma, cudaFuncAttributeMaxDynamicSharedMemorySize,
                         SMEM_CONV2);

    k_style<<<512, 256>>>(style, mod_w, mod_b);
    k_wsq<<<(COUT * CIN + 255) / 256, 256>>>(conv_w);
    k_demod<<<512, 256>>>();

    k_zero_xt<<<4096, 256>>>();
    k_prep_x<<<BATCH * 64 * 16 * 2, 256>>>(x);
    k_prep_w<<<(WT_ELEMS + 255) / 256, 256>>>(conv_w);

    k_conv_mma<<<BATCH * 4 * 8 * 4, 256, SMEM_CONV2>>>(act_b);

    k_filter<<<BATCH * COUT, 256, SMEM_FILT_BYTES>>>(up_f, down_f, out);
}

// round 9
// speedup vs baseline: 2.9691x; 1.0701x over previous
#include <cuda_runtime.h>
#include <cuda_bf16.h>
#include <math.h>

// ---------------------------------------------------------------------------
// AliasFreeConv: modulated 3x3 conv (demod) + 2x up (12-tap) + lrelu + 2x down
// Conv: bf16 split-precision (3-pass) implicit GEMM on mma.sync + ldmatrix.
// Launch order: pre1, pre2, prep_x, conv(#4 - profiled), filter.
// ---------------------------------------------------------------------------

#define BATCH 8
#define CIN   512
#define COUT  512
#define HW    64
#define HC    62
#define HU    128
#define NTAPS 12
#define XP    68              // padded spatial for channels-last input

#define LIN_SCALE 0.044194173824159216f   // 1/sqrt(512)
#define WSCALE    0.014731391274719742f   // 1/sqrt(512*9)
#define WSCALE2   2.170138888888889e-4f   // 1/4608
#define EPSV      1e-8f
#define NEG_SLOPE 0.2f
#define LRELU_SC  1.4142135623730951f

#define XT_ELEMS (BATCH*XP*XP*512)        // 18,939,904
#define WT_ELEMS (9*512*512)              // 2,359,296

// ------------------------- scratch (device globals) ------------------------
__device__ float g_s  [BATCH*CIN];
__device__ float g_g  [BATCH*COUT];
__device__ float g_wsq[COUT*CIN];
__device__ float g_A  [BATCH*COUT*HC*HC];               // conv output (63 MB)
__device__ __align__(16) __nv_bfloat16 g_xhi[XT_ELEMS]; // x*wscale*s, hi part
__device__ __align__(16) __nv_bfloat16 g_xlo[XT_ELEMS]; // lo part
__device__ __align__(16) __nv_bfloat16 g_whi[WT_ELEMS]; // [tap][co][ci]
__device__ __align__(16) __nv_bfloat16 g_wlo[WT_ELEMS];

// ------------------------- PTX helpers -------------------------------------
__device__ __forceinline__ unsigned smem_u32(const void* p) {
    unsigned a;
    asm("{ .reg .u64 t; cvta.to.shared.u64 t, %1; cvt.u32.u64 %0, t; }"
        : "=r"(a) : "l"(p));
    return a;
}
__device__ __forceinline__ void cp16(unsigned dst, const void* src) {
    asm volatile("cp.async.cg.shared.global [%0], [%1], 16;"
                 :: "r"(dst), "l"(src) : "memory");
}
__device__ __forceinline__ void cp_commit() {
    asm volatile("cp.async.commit_group;" ::: "memory");
}
__device__ __forceinline__ void cp_wait0() {
    asm volatile("cp.async.wait_group 0;" ::: "memory");
}
__device__ __forceinline__ void cp_wait1() {
    asm volatile("cp.async.wait_group 1;" ::: "memory");
}
#define MMA16816(d, a0, a1, a2, a3, b0, b1) \
    asm volatile("mma.sync.aligned.m16n8k16.row.col.f32.bf16.bf16.f32 " \
        "{%0,%1,%2,%3}, {%4,%5,%6,%7}, {%8,%9}, {%0,%1,%2,%3};" \
        : "+f"((d)[0]), "+f"((d)[1]), "+f"((d)[2]), "+f"((d)[3]) \
        : "r"(a0), "r"(a1), "r"(a2), "r"(a3), "r"(b0), "r"(b1))
#define LDSM4(r0, r1, r2, r3, addr) \
    asm volatile("ldmatrix.sync.aligned.m8n8.x4.shared.b16 {%0,%1,%2,%3}, [%4];" \
        : "=r"(r0), "=r"(r1), "=r"(r2), "=r"(r3) : "r"(addr))

// ------------------------- L1: style + wsq + zero x_t ----------------------
__global__ __launch_bounds__(256)
void k_pre1(const float* __restrict__ style, const float* __restrict__ mod_w,
            const float* __restrict__ mod_b, const float* __restrict__ cw) {
    int bid = blockIdx.x;
    int tid = threadIdx.x;
    if (bid < 512) {
        // style: s = style @ (mod_w*ls)^T + mod_b   (4096 warps)
        int w    = bid * 8 + (tid >> 5);
        int lane = tid & 31;
        int b = w >> 9, c = w & 511;
        const float* sp = style + b * 512;
        const float* mp = mod_w + c * 512;
        float sum = 0.f;
        #pragma unroll 4
        for (int d = lane; d < 512; d += 32) sum += sp[d] * mp[d];
        #pragma unroll
        for (int off = 16; off; off >>= 1)
            sum += __shfl_xor_sync(0xffffffffu, sum, off);
        if (lane == 0) g_s[w] = sum * LIN_SCALE + mod_b[c];
    } else if (bid < 1536) {
        // wsq[co,ci] = sum_k conv_w^2
        int i = (bid - 512) * 256 + tid;
        if (i < COUT * CIN) {
            float s = 0.f;
            #pragma unroll
            for (int k = 0; k < 9; k++) { float v = cw[i * 9 + k]; s += v * v; }
            g_wsq[i] = s;
        }
    } else {
        // zero padded x_t buffers (16B granules)
        uint4 z = make_uint4(0u, 0u, 0u, 0u);
        uint4* a = reinterpret_cast<uint4*>(g_xhi);
        uint4* bb = reinterpret_cast<uint4*>(g_xlo);
        int n = XT_ELEMS / 8;
        for (int i = (bid - 1536) * 256 + tid; i < n; i += 4096 * 256) {
            a[i] = z; bb[i] = z;
        }
    }
}

// ------------------------- L2: demod + prep_w ------------------------------
__global__ __launch_bounds__(256)
void k_pre2(const float* __restrict__ cw) {
    int bid = blockIdx.x;
    int tid = threadIdx.x;
    if (bid < 512) {
        // g = demod/(1+eps)
        int w    = bid * 8 + (tid >> 5);
        int lane = tid & 31;
        int b = w >> 9, co = w & 511;
        const float* sp = g_s   + b  * 512;
        const float* wq = g_wsq + co * 512;
        float sum = 0.f;
        #pragma unroll 4
        for (int d = lane; d < 512; d += 32) {
            float sv = sp[d]; sum += sv * sv * wq[d];
        }
        #pragma unroll
        for (int off = 16; off; off >>= 1)
            sum += __shfl_xor_sync(0xffffffffu, sum, off);
        if (lane == 0) g_g[w] = 1.0f / ((1.0f + EPSV) * sqrtf(WSCALE2 * sum + EPSV));
    } else {
        // weights -> [tap][co][ci] bf16 hi/lo
        int i = (bid - 512) * 256 + tid;
        if (i < WT_ELEMS) {
            int ci  = i & 511;
            int co  = (i >> 9) & 511;
            int tap = i >> 18;
            float v = cw[(co * 512 + ci) * 9 + tap];
            __nv_bfloat16 hi = __float2bfloat16(v);
            __nv_bfloat16 lo = __float2bfloat16(v - __bfloat162float(hi));
            g_whi[i] = hi;
            g_wlo[i] = lo;
        }
    }
}

// ------------------------- L3: x -> channels-last bf16 hi/lo ---------------
__global__ __launch_bounds__(256)
void k_prep_x(const float* __restrict__ x) {
    __shared__ float t[32][33];
    int bid  = blockIdx.x;                 // b(8) * y(64) * ciT(16) * xT(2)
    int xt   = bid & 1;
    int ci_t = (bid >> 1) & 15;
    int y    = (bid >> 5) & 63;
    int b    = bid >> 11;
    int tx = threadIdx.x & 31, ty = threadIdx.x >> 5;   // (32, 8)

    #pragma unroll
    for (int j = 0; j < 4; j++) {
        int ci = ci_t * 32 + ty + 8 * j;
        int xx = xt * 32 + tx;
        float v = x[((((b << 9) + ci) << 6) + y) * 64 + xx];
        t[ty + 8 * j][tx] = v * (WSCALE * g_s[(b << 9) + ci]);
    }
    __syncthreads();
    #pragma unroll
    for (int j = 0; j < 4; j++) {
        int xx = xt * 32 + ty + 8 * j;
        int ci = ci_t * 32 + tx;
        float v = t[tx][ty + 8 * j];
        __nv_bfloat16 hi = __float2bfloat16(v);
        __nv_bfloat16 lo = __float2bfloat16(v - __bfloat162float(hi));
        long o = ((long)(b * XP + y) * XP + xx) * 512 + ci;
        g_xhi[o] = hi;
        g_xlo[o] = lo;
    }
}

// ------------------------- L4: mma.sync conv (ldmatrix) --------------------
// CTA tile: M=128 co x N=128 pixels (8y x 16x). 8 warps = 2(m) x 4(n),
// warp tile 64x32. K loop: 3 passes x 8 ci-chunks(64) x 9 taps = 216 iters
// of K=64. W triple-buffered cp.async prefetch distance 2 (wait_group 1);
// X tile (10x18 pixels x 64ci) double-buffered, staged once per chunk.
// smem: Xs0 @0, Xs1 @25920, Ws @51840 + buf*18432 (3 bufs) -> 107136 B.
#define XS_STRIDE 144
#define OFF_WS    51840
#define WS_BYTES  18432
#define XS_BYTES  25920
#define SMEM_CONV2 107136

__global__ __launch_bounds__(256, 2)
void k_conv_mma(const float* __restrict__ act_b) {
    extern __shared__ __align__(16) char smc[];
    unsigned sbase = smem_u32(smc);

    int tid  = threadIdx.x;
    int wid  = tid >> 5, lane = tid & 31;
    int g    = lane >> 2, t4 = lane & 3;
    int wm   = wid >> 2;                      // 0..1 -> co offset wm*64
    int wn   = wid & 3;                       // 0..3 -> pixel offset wn*32

    int bidx = blockIdx.x;                    // 1024 = b(8)*coT(4)*yT(8)*xT(4)
    int xT   = bidx & 3;
    int yT   = (bidx >> 2) & 7;
    int coT  = (bidx >> 5) & 3;
    int b    = bidx >> 7;
    int co0  = coT << 7;
    int y0   = yT << 3;
    int x0   = xT << 4;

    const __nv_bfloat16* xhiB = g_xhi + (long)b * XP * XP * 512;
    const __nv_bfloat16* xloB = g_xlo + (long)b * XP * XP * 512;

    float acc[4][4][4];
    #pragma unroll
    for (int mi = 0; mi < 4; mi++)
        #pragma unroll
        for (int ni = 0; ni < 4; ni++)
            #pragma unroll
            for (int q = 0; q < 4; q++) acc[mi][ni][q] = 0.f;

    // ---- staging helpers ----
    auto stageW = [&](int it, int buf) {
        int pass = it / 72;
        int r    = it - pass * 72;
        int tap  = r % 9;
        int ci0  = (r / 9) << 6;
        const __nv_bfloat16* wp =
            ((pass == 1) ? g_wlo : g_whi) + ((long)tap << 18) + (long)co0 * 512 + ci0;
        unsigned dst = sbase + OFF_WS + buf * WS_BYTES;
        #pragma unroll
        for (int k = 0; k < 4; k++) {                 // 1024 x 16B
            int c = tid + (k << 8);
            int row = c >> 3, cc = c & 7;
            cp16(dst + row * XS_STRIDE + (cc << 4), wp + row * 512 + (cc << 3));
        }
    };
    auto stageX = [&](int j, int buf) {               // j = pass*8 + chunk
        int pass = j >> 3;
        int ci0  = (j & 7) << 6;
        const __nv_bfloat16* xp = ((pass < 2) ? xhiB : xloB) + ci0;
        unsigned dst = sbase + buf * XS_BYTES;
        for (int c = tid; c < 180 * 8; c += 256) {
            int row = c >> 3, cc = c & 7;
            int gy = y0 + row / 18, gx = x0 + row % 18;
            cp16(dst + row * XS_STRIDE + (cc << 4),
                 xp + (long)(gy * XP + gx) * 512 + (cc << 3));
        }
    };

    // prologue: X(0), W(0), W(1) resident before iter 0
    stageX(0, 0);
    stageW(0, 0);
    cp_commit();
    stageW(1, 1);
    cp_commit();
    cp_wait0();
    __syncthreads();

    // per-lane ldmatrix base offsets
    unsigned aBaseRow = (unsigned)((wm * 64 + (lane & 15)) * XS_STRIDE)
                        + (((unsigned)lane >> 4) << 4);
    int pxc = (((lane >> 4) & 1) << 3) + (lane & 7);
    unsigned bCol16 = (((unsigned)lane >> 3) & 1) << 4;

    #pragma unroll 1
    for (int i = 0; i < 216; i++) {
        if (i + 2 < 216) stageW(i + 2, (i + 2) % 3);
        if ((i % 9) == 0) {
            int jn = i / 9 + 1;
            if (jn < 24) stageX(jn, jn & 1);
        }
        cp_commit();

        // compute iter i
        {
            int r   = i % 72;
            int tap = r % 9;
            int ky  = tap / 3, kx = tap - 3 * (tap / 3);
            unsigned aB = sbase + OFF_WS + (unsigned)(i % 3) * WS_BYTES + aBaseRow;
            unsigned xO = sbase + (unsigned)((i / 9) & 1) * XS_BYTES;
            unsigned bA0 = xO + (unsigned)(((wn * 2 + ky) * 18 + pxc + kx) * XS_STRIDE)
                           + bCol16;
            unsigned bA1 = bA0 + 18 * XS_STRIDE;

            #pragma unroll
            for (int kb = 0; kb < 4; kb++) {
                unsigned bq0, bq1, bq2, bq3, bq4, bq5, bq6, bq7;
                LDSM4(bq0, bq1, bq2, bq3, bA0 + kb * 32);
                LDSM4(bq4, bq5, bq6, bq7, bA1 + kb * 32);
                #pragma unroll
                for (int mi = 0; mi < 4; mi++) {
                    unsigned a0, a1, a2, a3;
                    LDSM4(a0, a1, a2, a3, aB + mi * (16 * XS_STRIDE) + kb * 32);
                    MMA16816(acc[mi][0], a0, a1, a2, a3, bq0, bq1);
                    MMA16816(acc[mi][1], a0, a1, a2, a3, bq2, bq3);
                    MMA16816(acc[mi][2], a0, a1, a2, a3, bq4, bq5);
                    MMA16816(acc[mi][3], a0, a1, a2, a3, bq6, bq7);
                }
            }
        }

        cp_wait1();          // keep only the group committed THIS iter in flight
        __syncthreads();
    }

    // epilogue: D[co][pix] * demod + bias -> g_A
    #pragma unroll
    for (int mi = 0; mi < 4; mi++) {
        int coL = co0 + wm * 64 + mi * 16 + g;
        int coH = coL + 8;
        float ggL = g_g[(b << 9) + coL], bbL = act_b[coL];
        float ggH = g_g[(b << 9) + coH], bbH = act_b[coH];
        float* apL = g_A + (long)((b << 9) + coL) * (HC * HC);
        float* apH = g_A + (long)((b << 9) + coH) * (HC * HC);
        #pragma unroll
        for (int ni = 0; ni < 4; ni++) {
            int p0 = wn * 32 + ni * 8;
            int py = p0 >> 4, px = (p0 & 15) + 2 * t4;
            int oy = y0 + py, ox = x0 + px;
            if (oy < HC) {
                if (ox < HC) {
                    apL[oy * HC + ox] = acc[mi][ni][0] * ggL + bbL;
                    apH[oy * HC + ox] = acc[mi][ni][2] * ggH + bbH;
                }
                if (ox + 1 < HC) {
                    apL[oy * HC + ox + 1] = acc[mi][ni][1] * ggL + bbL;
                    apH[oy * HC + ox + 1] = acc[mi][ni][3] * ggH + bbH;
                }
            }
        }
    }
}

// ------------------------- L5: fused filter chain --------------------------
#define SMEM_FILT_BYTES (28440 * 4)

__global__ __launch_bounds__(256)
void k_filter(const float* __restrict__ uf, const float* __restrict__ df,
              float* __restrict__ out) {
    extern __shared__ float sm[];
    float* sA  = sm;
    float* sB  = sm + 3906;
    float* sC  = sm + 11904;
    float* sD  = sm;
    float* kfu = sm + 28416;
    float* kfd = sm + 28428;

    int p   = blockIdx.x;
    int tid = threadIdx.x;

    if (tid < NTAPS)          kfu[tid] = uf[tid] * 2.0f;
    else if (tid < 2 * NTAPS) kfd[tid - NTAPS] = df[tid - NTAPS];

    const float* Ap = g_A + (long)p * (HC * HC);
    for (int i = tid; i < HC * HC; i += 256) {
        int r = i / HC, c = i - r * HC;
        sA[r * 63 + c] = Ap[i];
    }
    __syncthreads();

    for (int i = tid; i < HC * HU; i += 256) {
        int n = i & 127, y = i >> 7;
        const float* row = sA + y * 63;
        float acc = 0.f;
        int s0 = (n + 3) & 1;
        #pragma unroll
        for (int q = 0; q < 6; q++) {
            int s = s0 + 2 * q;
            int j = (n + 3 - s) >> 1;
            if ((unsigned)j < (unsigned)HC) acc += kfu[s] * row[j];
        }
        sB[y * 129 + n] = acc;
    }
    __syncthreads();

    for (int i = tid; i < HU * HU; i += 256) {
        int xcol = i & 127, m = i >> 7;
        float acc = 0.f;
        int s0 = (m + 3) & 1;
        #pragma unroll
        for (int q = 0; q < 6; q++) {
            int s = s0 + 2 * q;
            int j = (m + 3 - s) >> 1;
            if ((unsigned)j < (unsigned)HC) acc += kfu[s] * sB[j * 129 + xcol];
        }
        acc = (acc >= 0.f ? acc : NEG_SLOPE * acc) * LRELU_SC;
        sC[m * 129 + xcol] = acc;
    }
    __syncthreads();

    for (int i = tid; i < HU * 64; i += 256) {
        int n = i & 63, y = i >> 6;
        const float* row = sC + y * 129;
        float acc = 0.f;
        #pragma unroll
        for (int s = 0; s < NTAPS; s++) {
            int j = 2 * n + 6 - s;
            if ((unsigned)j < (unsigned)HU) acc += kfd[s] * row[j];
        }
        sD[y * 65 + n] = acc;
    }
    __syncthreads();

    float* op = out + (long)p * (64 * 64);
    for (int i = tid; i < 64 * 64; i += 256) {
        int xcol = i & 63, m = i >> 6;
        float acc = 0.f;
        #pragma unroll
        for (int s = 0; s < NTAPS; s++) {
            int j = 2 * m + 6 - s;
            if ((unsigned)j < (unsigned)HU) acc += kfd[s] * sD[j * 65 + xcol];
        }
        op[i] = acc;
    }
}

// ---------------------------------------------------------------------------
extern "C" void kernel_launch(void* const* d_in, const int* in_sizes, int n_in,
                              void* d_out, int out_size) {
    const float* x      = (const float*)d_in[0];
    const float* style  = (const float*)d_in[1];
    const float* mod_w  = (const float*)d_in[2];
    const float* mod_b  = (const float*)d_in[3];
    const float* conv_w = (const float*)d_in[4];
    const float* act_b  = (const float*)d_in[5];
    const float* up_f   = (const float*)d_in[6];
    const float* down_f = (const float*)d_in[7];
    float* out = (float*)d_out;

    cudaFuncSetAttribute(k_filter, cudaFuncAttributeMaxDynamicSharedMemorySize,
                         SMEM_FILT_BYTES);
    cudaFuncSetAttribute(k_conv_mma, cudaFuncAttributeMaxDynamicSharedMemorySize,
                         SMEM_CONV2);

    k_pre1<<<1536 + 4096, 256>>>(style, mod_w, mod_b, conv_w);   // #1
    k_pre2<<<512 + 9216, 256>>>(conv_w);                          // #2
    k_prep_x<<<BATCH * 64 * 16 * 2, 256>>>(x);                    // #3
    k_conv_mma<<<BATCH * 4 * 8 * 4, 256, SMEM_CONV2>>>(act_b);    // #4 (profiled)
    k_filter<<<BATCH * COUT, 256, SMEM_FILT_BYTES>>>(up_f, down_f, out);  // #5
}